// round 11
// baseline (speedup 1.0000x reference)
#include <cuda_runtime.h>
#include <math.h>

#define TT   1024
#define NA   512
#define MB   64
#define NM   32768                       // NA*MB elements per timestep slab
#define HALF ((size_t)NM * TT)           // elements per output tensor

// ---------------- scratch (device globals; allocation is forbidden) -------------
__device__ float g_X2[(size_t)TT * NM];          // [t][n][m] transposed x; reused for Y
__device__ float g_P [(size_t)TT * NM];          // [t][a][m] = Wax@x + ba
__device__ float g_A [((size_t)TT + 1) * NM];    // slot 0 = a0; slot t+1 = a_{t+1}
__device__ int   g_doneq[2][TT + 1][8];          // a-flags: [mh][slot][k-octant], ==8 done
__device__ int   g_doneP[TT][8];                 // P-flags: [t][row-octant], ==1 done
__device__ int   g_doneA[TT + 1];                // slab-complete: ==128 done

// ---------------- init: flags, seed a0 into slot 0 -------------------------------
__global__ void k_init(const float* __restrict__ a0) {
    if (blockIdx.x == 0) {
        int* f1 = &g_doneq[0][0][0];
        for (int i = threadIdx.x; i < 2 * (TT + 1) * 8; i += blockDim.x) {
            int s = (i >> 3) % (TT + 1);
            f1[i] = (s == 0) ? 8 : 0;
        }
        int* f2 = &g_doneP[0][0];
        for (int i = threadIdx.x; i < TT * 8; i += blockDim.x) f2[i] = 0;
        for (int i = threadIdx.x; i <= TT; i += blockDim.x) g_doneA[i] = 0;
    } else {
        int idx = (blockIdx.x - 1) * 256 + threadIdx.x;
        g_A[idx] = a0[idx];
    }
}

// ---------------- 32x32 tiled transpose -------------------------------------------
__device__ __forceinline__ void trans_body(const float* __restrict__ src,
                                           float* __restrict__ dst, int R, int C) {
    __shared__ float tile[32][33];
    int c0 = blockIdx.x * 32, r0 = blockIdx.y * 32;
    int tx = threadIdx.x, ty = threadIdx.y;
#pragma unroll
    for (int i = 0; i < 32; i += 8)
        tile[ty + i][tx] = src[(size_t)(r0 + ty + i) * C + (c0 + tx)];
    __syncthreads();
#pragma unroll
    for (int i = 0; i < 32; i += 8)
        dst[(size_t)(c0 + ty + i) * R + (r0 + tx)] = tile[tx][ty + i];
}
__global__ __launch_bounds__(256) void k_trans_x(const float* __restrict__ x) {
    trans_body(x, g_X2, NM, TT);          // [32768][1024] -> [1024][32768]
}
__global__ __launch_bounds__(256) void k_trans_a(float* __restrict__ out) {
    trans_body(g_A + NM, out, TT, NM);    // [1024][32768] -> [32768][1024]
}
__global__ __launch_bounds__(256) void k_trans_y(float* __restrict__ out) {
    trans_body(g_X2, out, TT, NM);
}

// ---------------- gemm role: C_t[64r x 64m] = W @ X_t (+bias/softmax) -------------
template <bool SOFTMAX>
__device__ __forceinline__ void gemm_role(float* smraw,
                                          const float* __restrict__ W,
                                          const float* __restrict__ bias,
                                          const float* __restrict__ Xbase,
                                          float* __restrict__ Ybase, int bid2) {
    float (*Ws)[32] = (float(*)[32])smraw;              // 64x32
    float (*Xs)[64] = (float(*)[64])(smraw + 64 * 32);  // 32x64

    int t  = bid2 >> 3;
    int rb = bid2 & 7;
    const float* X = Xbase + (size_t)t * NM;
    float*       Y = Ybase + (size_t)t * NM;
    int tid = threadIdx.x;
    int mq  = tid & 15;
    int rq  = tid >> 4;
    int r0  = rb * 64 + rq * 4;

    if (SOFTMAX) {
        // wait: slab t+1 of g_A fully produced (also implies gemmP(t) all done
        // reading g_X2[t], so our write below has no WAR hazard)
        if (tid == 0) {
            int v;
            do {
                asm volatile("ld.acquire.gpu.global.u32 %0, [%1];"
                             : "=r"(v) : "l"(&g_doneA[t + 1]));
            } while (v < 128);
        }
        __syncthreads();
    }

    float acc[4][4];
#pragma unroll
    for (int i = 0; i < 4; i++)
#pragma unroll
        for (int j = 0; j < 4; j++) acc[i][j] = 0.f;

    for (int kt = 0; kt < 16; kt++) {
        __syncthreads();
        {
            int f4 = tid;
            int row = f4 >> 3, c4 = f4 & 7;
            *(float4*)&Ws[row][c4 * 4] =
                *(const float4*)&W[(size_t)(rb * 64 + row) * NA + kt * 32 + c4 * 4];
            f4 = tid + 256;
            row = f4 >> 3; c4 = f4 & 7;
            *(float4*)&Ws[row][c4 * 4] =
                *(const float4*)&W[(size_t)(rb * 64 + row) * NA + kt * 32 + c4 * 4];
        }
        {
            int f4 = tid;
            int k = f4 >> 4, m4 = f4 & 15;
            *(float4*)&Xs[k][m4 * 4] =
                *(const float4*)&X[(size_t)(kt * 32 + k) * MB + m4 * 4];
            f4 = tid + 256;
            k = f4 >> 4; m4 = f4 & 15;
            *(float4*)&Xs[k][m4 * 4] =
                *(const float4*)&X[(size_t)(kt * 32 + k) * MB + m4 * 4];
        }
        __syncthreads();
#pragma unroll 8
        for (int k = 0; k < 32; k++) {
            float4 xv = *(const float4*)&Xs[k][mq * 4];
#pragma unroll
            for (int i = 0; i < 4; i++) {
                float w = Ws[rq * 4 + i][k];
                acc[i][0] += w * xv.x;
                acc[i][1] += w * xv.y;
                acc[i][2] += w * xv.z;
                acc[i][3] += w * xv.w;
            }
        }
    }

    if (!SOFTMAX) {
#pragma unroll
        for (int i = 0; i < 4; i++) {
            float b = bias[r0 + i];
            float4 v = make_float4(acc[i][0] + b, acc[i][1] + b,
                                   acc[i][2] + b, acc[i][3] + b);
            *(float4*)&Y[(size_t)(r0 + i) * MB + mq * 4] = v;
        }
        __syncthreads();                  // all output stores done CTA-wide
        if (tid == 0)
            asm volatile("red.release.gpu.global.add.u32 [%0], %1;"
                         :: "l"(&g_doneP[t][rb]), "r"(1) : "memory");
    } else {
#pragma unroll
        for (int i = 0; i < 4; i++) {
            float b  = bias[r0 + i];
            float v0 = acc[i][0] + b, v1 = acc[i][1] + b;
            float v2 = acc[i][2] + b, v3 = acc[i][3] + b;
            float mx = fmaxf(fmaxf(v0, v1), fmaxf(v2, v3));
#pragma unroll
            for (int o = 1; o < 16; o <<= 1)
                mx = fmaxf(mx, __shfl_xor_sync(0xffffffffu, mx, o));
            float e0 = __expf(v0 - mx), e1 = __expf(v1 - mx);
            float e2 = __expf(v2 - mx), e3 = __expf(v3 - mx);
            float s = e0 + e1 + e2 + e3;
#pragma unroll
            for (int o = 1; o < 16; o <<= 1)
                s += __shfl_xor_sync(0xffffffffu, s, o);
            float inv = 1.0f / s;
            *(float4*)&Y[(size_t)(r0 + i) * MB + mq * 4] =
                make_float4(e0 * inv, e1 * inv, e2 * inv, e3 * inv);
        }
    }
}

// ---------------- recur role (R7 v4 + per-octant P wait) --------------------------
#define AST 33
#define SM_WAS (8 * 512)                  // 16 KB
#define SM_AS  (512 * AST)                // 67584 B
#define SM_PART (8 * 8 * 32)              // 8 KB
#define MAIN_SMEM ((SM_WAS + SM_AS + SM_PART) * 4)

__device__ __forceinline__ void recur_role(float* sm, const float* __restrict__ Waa,
                                           int bid) {
    float* Was  = sm;                     // [8 rows][512 k]
    float* As   = sm + SM_WAS;            // [512 k][33]
    float* part = sm + SM_WAS + SM_AS;    // [8 ks][8 r][32 m]

    int rb  = bid >> 1;                   // 64 row blocks of 8
    int mh  = bid & 1;                    // m half
    int tid = threadIdx.x;
    int w   = tid >> 5;                   // warp = k-octant 0..7
    int l   = tid & 31;                   // lane = m

    // stage Waa rows once: 8 x 512 = 1024 float4, 4/thread
#pragma unroll
    for (int i = 0; i < 4; i++) {
        int f4  = tid + i * 256;
        int row = f4 >> 7, c4 = f4 & 127;
        float4 v = *(const float4*)&Waa[(size_t)(rb * 8 + row) * NA + c4 * 4];
        *(float4*)&Was[row * 512 + c4 * 4] = v;
    }
    __syncthreads();

    const size_t o  = (size_t)(rb * 8 + w) * MB + mh * 32 + l;   // my output elem
    const int*   fl = &g_doneq[mh][0][w];
    int oct_out = rb >> 3;                // octant of my P rows / my output rows
    float* dst = As + w * 64 * AST;
    const float* ab = As + w * 64 * AST + l;
    const float* wb = Was + w * 64;

    for (int s = 0; s < TT; s++) {
        // wait: a-slab s octant w ready, and P slab s (my row octant) ready
        {
            int v;
            do {
                asm volatile("ld.acquire.gpu.global.u32 %0, [%1];"
                             : "=r"(v) : "l"(fl + (size_t)s * 8));
            } while (v < 8);
            do {
                asm volatile("ld.acquire.gpu.global.u32 %0, [%1];"
                             : "=r"(v) : "l"(&g_doneP[s][oct_out]));
            } while (v < 1);
        }
        __syncwarp();

        float pv = g_P[(size_t)s * NM + o];

        // stage my octant: 64 k x 32 m = 512 float4, 16 per lane
        const float* src = g_A + (size_t)s * NM + (size_t)w * 64 * MB + mh * 32;
#pragma unroll
        for (int i = 0; i < 16; i++) {
            int idx = l + i * 32;
            int kq = idx >> 3, c4 = idx & 7;
            float4 a4 = *(const float4*)&src[(size_t)kq * MB + c4 * 4];
            float* d = &dst[kq * AST + c4 * 4];
            d[0] = a4.x; d[1] = a4.y; d[2] = a4.z; d[3] = a4.w;
        }
        __syncwarp();

        // compute: 8 rows x 64 k, m = lane
        float acc[8];
#pragma unroll
        for (int r = 0; r < 8; r++) acc[r] = 0.f;
#pragma unroll
        for (int u = 0; u < 64; u += 4) {
            float a0 = ab[(u + 0) * AST];
            float a1 = ab[(u + 1) * AST];
            float a2 = ab[(u + 2) * AST];
            float a3 = ab[(u + 3) * AST];
#pragma unroll
            for (int r = 0; r < 8; r++) {
                float4 wv = *(const float4*)&wb[r * 512 + u];   // warp-uniform
                acc[r] += wv.x * a0;
                acc[r] += wv.y * a1;
                acc[r] += wv.z * a2;
                acc[r] += wv.w * a3;
            }
        }
#pragma unroll
        for (int r = 0; r < 8; r++)
            part[(w * 8 + r) * 32 + l] = acc[r];
        __syncthreads();

        // reduce over 8 octants: thread (w,l) owns (row w, m l)
        float z = pv;
#pragma unroll
        for (int ks = 0; ks < 8; ks++)
            z += part[(ks * 8 + w) * 32 + l];
        g_A[(size_t)(s + 1) * NM + o] = tanhf(z);

        __syncthreads();
        if (tid == 0) {
            asm volatile("red.release.gpu.global.add.u32 [%0], %1;"
                         :: "l"(&g_doneq[mh][s + 1][oct_out]), "r"(1) : "memory");
            asm volatile("red.release.gpu.global.add.u32 [%0], %1;"
                         :: "l"(&g_doneA[s + 1]), "r"(1) : "memory");
        }
    }
}

// ---------------- fused main: recur + gemmP + gemmY in one launch -----------------
#define GP_BASE 128
#define GY_BASE (128 + 8192)

__global__ __launch_bounds__(256) void k_main(const float* __restrict__ Waa,
                                              const float* __restrict__ Wax,
                                              const float* __restrict__ ba,
                                              const float* __restrict__ Wya,
                                              const float* __restrict__ by) {
    extern __shared__ float sm[];
    int bid = blockIdx.x;
    if (bid < GP_BASE) {
        recur_role(sm, Waa, bid);
    } else if (bid < GY_BASE) {
        gemm_role<false>(sm, Wax, ba, g_X2, g_P, bid - GP_BASE);
    } else {
        gemm_role<true>(sm, Wya, by, g_A + NM, g_X2, bid - GY_BASE);
    }
}

// ---------------- launch ----------------------------------------------------------
extern "C" void kernel_launch(void* const* d_in, const int* in_sizes, int n_in,
                              void* d_out, int out_size) {
    (void)in_sizes; (void)n_in; (void)out_size;
    const float* x   = (const float*)d_in[0];
    const float* a0  = (const float*)d_in[1];
    const float* Waa = (const float*)d_in[2];
    const float* Wax = (const float*)d_in[3];
    const float* Wya = (const float*)d_in[4];
    const float* ba  = (const float*)d_in[5];
    const float* by  = (const float*)d_in[6];
    float* out = (float*)d_out;

    cudaFuncSetAttribute(k_main, cudaFuncAttributeMaxDynamicSharedMemorySize,
                         MAIN_SMEM);

    k_init<<<129, 256>>>(a0);
    k_trans_x<<<dim3(TT / 32, NM / 32), dim3(32, 8)>>>(x);     // x -> [t][n][m]
    k_main<<<128 + 8192 + 8192, 256, MAIN_SMEM>>>(Waa, Wax, ba, Wya, by);
    k_trans_a<<<dim3(NM / 32, TT / 32), dim3(32, 8)>>>(out);   // -> [n][m][t]
    k_trans_y<<<dim3(NM / 32, TT / 32), dim3(32, 8)>>>(out + HALF);
}